// round 9
// baseline (speedup 1.0000x reference)
#include <cuda_runtime.h>
#include <cuda_fp16.h>
#include <cstdint>
#include <stdint.h>

#define BB    32
#define NN    96
#define DD    64
#define LL    5
#define NPAIR 9216            // N*N
#define PTOT  294912          // B*N*N
#define BEP   24576           // B*EP
#define EV    5
#define MAXPAIRS 49152

// ---- scratch (device globals; no allocation allowed) ----
__device__ __align__(16) float  g_T0 [PTOT*DD];
__device__ __align__(16) float  g_T1 [PTOT*DD];
__device__ __align__(16) __half g_h1 [PTOT*DD];   // h1[b,u,w,d] fp16
__device__ __align__(16) float  g_h2 [PTOT*DD];   // h2[b,w,v,d] fp32 (edge slots)
__device__ int   g_aux[PTOT];
__device__ int   g_A  [PTOT];
__device__ int   g_deg[BB*NN];
__device__ int   g_nbr[BB*NN*NN];
__device__ int   g_pairs[MAXPAIRS];
__device__ int   g_npairs;
__device__ float g_sum[BB*DD];
__device__ float g_sq [BB*DD];
__device__ float g_scale[BB*DD];
__device__ float g_shift[BB*DD];
__device__ float g_pool[BB*DD];

// k1_fused dynamic smem (bytes), h1 path:
//   [0:34816) sA(128x72 fp16) reused as sO(128x68 f32) | [34816:44032) sB(64x72 fp16)
//   [44032:44288) bias | [44288:44544) sc | [44544:44800) sh
// h2 path: [0:17408) sIn 64x68 f32 | [17408:33792) sW 64x64 f32 | [33792:34048) sB | [34048:34304) sP
#define SMEM_K1 45312

// k23 dynamic smem (bytes):
//   [0:9216)     sWm 64x72 fp16
//   [9216:23040) sMhi 96x72 fp16
//   [23040:36864) sMlo 96x72 fp16
//   [36864:62976) sh2 96x64 f32 (staging)  reused as sO 96x68 f32
//   [62976:63360) snbr 96 int
//   [63360:63616) sSc | [63616:63872) sSh | [63872:64128) sSum | [64128:64384) sSq
#define SMEM_K23 64384

__device__ __forceinline__ uint32_t smem_u32(const void* p) {
    uint32_t a;
    asm("{ .reg .u64 t; cvta.to.shared.u64 t, %1; cvt.u32.u64 %0, t; }"
        : "=r"(a) : "l"(p));
    return a;
}
__device__ __forceinline__ void ldmA(uint32_t a[4], uint32_t addr) {
    asm volatile("ldmatrix.sync.aligned.m8n8.x4.shared.b16 {%0,%1,%2,%3}, [%4];"
        : "=r"(a[0]), "=r"(a[1]), "=r"(a[2]), "=r"(a[3]) : "r"(addr));
}
__device__ __forceinline__ void ldmB(uint32_t b[2], uint32_t addr) {
    asm volatile("ldmatrix.sync.aligned.m8n8.x2.trans.shared.b16 {%0,%1}, [%2];"
        : "=r"(b[0]), "=r"(b[1]) : "r"(addr));
}
__device__ __forceinline__ void mma16816(float c[4], const uint32_t a[4],
                                         const uint32_t b[2]) {
    asm volatile(
        "mma.sync.aligned.m16n8k16.row.col.f32.f16.f16.f32 "
        "{%0,%1,%2,%3}, {%4,%5,%6,%7}, {%8,%9}, {%0,%1,%2,%3};"
        : "+f"(c[0]), "+f"(c[1]), "+f"(c[2]), "+f"(c[3])
        : "r"(a[0]), "r"(a[1]), "r"(a[2]), "r"(a[3]), "r"(b[0]), "r"(b[1]));
}

// ---------------------------------------------------------------------------
__global__ void k_init_clear() {
    int i = blockIdx.x * 256 + threadIdx.x;
    if (i < PTOT)   g_aux[i] = -1;
    if (i < BB*DD)  { g_pool[i] = 0.0f; g_sum[i] = 0.0f; g_sq[i] = 0.0f; }
    if (i < BB*NN)  g_deg[i] = 0;
    if (i == 0)     g_npairs = 0;
}

__global__ void k_scatter(const int* __restrict__ ei, const int* __restrict__ ea) {
    int e = blockIdx.x * 256 + threadIdx.x;
    if (e >= BEP) return;
    int a = ei[e];
    int bnode = ei[BEP + e];
    int g = a / NN, u = a % NN, v = bnode % NN;
    int lab = ea[e] & 7;
    atomicMax(&g_aux[g*NPAIR + u*NN + v], (e << 3) | lab);
    atomicMax(&g_aux[g*NPAIR + v*NN + u], ((e + BEP) << 3) | lab);
}

__global__ void k_decode() {
    int i = blockIdx.x * 256 + threadIdx.x;
    if (i >= PTOT) return;
    int av = g_aux[i];
    int a  = (av < 0) ? EV : (av & 7);
    g_A[i] = a;
    if (a != EV) {
        int b = i / NPAIR, r = i % NPAIR;
        int w = r / NN, v = r % NN;
        int slot = atomicAdd(&g_deg[b*NN + v], 1);
        g_nbr[(b*NN + v)*NN + slot] = w;
        int ps = atomicAdd(&g_npairs, 1);
        g_pairs[ps] = i;
    }
}

__global__ void k_initW(const int* __restrict__ x,
                        const float* __restrict__ nemb,
                        const float* __restrict__ eemb) {
    long q = (long)blockIdx.x * 256 + threadIdx.x;
    int p  = (int)(q >> 4);
    int d0 = ((int)q & 15) << 2;
    int b = p / NPAIR, r = p % NPAIR, u = r / NN, v = r % NN;
    int xu = x[b*NN + u], xv = x[b*NN + v], a = g_A[p];
    float4 hu = *(const float4*)(nemb + xu*DD + d0);
    float4 hv = *(const float4*)(nemb + xv*DD + d0);
    float4 he = *(const float4*)(eemb + a*DD + d0);
    float4 o;
    o.x = hu.x + hv.x + he.x;
    o.y = hu.y + hv.y + he.y;
    o.z = hu.z + hv.z + he.z;
    o.w = hu.w + hv.w + he.w;
    *(float4*)(g_T1 + (long)p*DD + d0) = o;
}

// ---------------------------------------------------------------------------
// k1_fused: blocks [0,2304): h1 = relu(relu_norm(T)@W1+b1) via HMMA, fp16 out.
//           blocks [2304,3072): h2 = relu(relu_norm(T)@W2+b2), edge rows, fp32.
__global__ void __launch_bounds__(256) k1_fused(const float* __restrict__ Tprev,
                                                const float* __restrict__ W1,
                                                const float* __restrict__ b1,
                                                const float* __restrict__ W2,
                                                const float* __restrict__ b2,
                                                int useNorm) {
    extern __shared__ char smem[];
    int t = threadIdx.x;
    if (blockIdx.x < 2304) {
        // ---------------- h1 path (HMMA) ----------------
        __half* sA   = (__half*)smem;
        float*  sO   = (float*)smem;
        __half* sB   = (__half*)(smem + 34816);
        float* sBias = (float*)(smem + 44032);
        float* sSc   = (float*)(smem + 44288);
        float* sSh   = (float*)(smem + 44544);
        int w = t >> 5, l = t & 31;
        int b = blockIdx.x / 72;
        long tile0 = (long)blockIdx.x * 128;

        for (int i = t; i < 4096; i += 256) {
            int k = i >> 6, n = i & 63;
            sB[k*72 + n] = __float2half(W1[i]);
        }
        if (t < 64) {
            sBias[t] = b1[t];
            sSc[t] = useNorm ? g_scale[b*64 + t] : 1.f;
            sSh[t] = useNorm ? g_shift[b*64 + t] : 0.f;
        }
        __syncthreads();
        {
            int r = t >> 1, c0 = (t & 1) * 32;
            const float* src = Tprev + (tile0 + r) * 64 + c0;
            __half h[32];
#pragma unroll
            for (int j = 0; j < 32; j += 4) {
                float4 f = *(const float4*)(src + j);
                if (useNorm) {
                    f.x = fmaxf(fmaf(f.x, sSc[c0+j+0], sSh[c0+j+0]), 0.f);
                    f.y = fmaxf(fmaf(f.y, sSc[c0+j+1], sSh[c0+j+1]), 0.f);
                    f.z = fmaxf(fmaf(f.z, sSc[c0+j+2], sSh[c0+j+2]), 0.f);
                    f.w = fmaxf(fmaf(f.w, sSc[c0+j+3], sSh[c0+j+3]), 0.f);
                }
                h[j+0] = __float2half(f.x);
                h[j+1] = __float2half(f.y);
                h[j+2] = __float2half(f.z);
                h[j+3] = __float2half(f.w);
            }
            uint4* dst = (uint4*)(sA + r*72 + c0);
#pragma unroll
            for (int j = 0; j < 4; j++) dst[j] = ((uint4*)h)[j];
        }
        __syncthreads();

        uint32_t sAu = smem_u32(sA);
        uint32_t sBu = smem_u32(sB);
        int r0 = w * 16;
        uint32_t aF[4][4];
#pragma unroll
        for (int kk = 0; kk < 4; kk++)
            ldmA(aF[kk], sAu + (uint32_t)(((r0 + (l & 15))*72 + kk*16 + 8*(l >> 4)) << 1));

        float acc[8][4];
#pragma unroll
        for (int j = 0; j < 8; j++)
#pragma unroll
            for (int q = 0; q < 4; q++) acc[j][q] = 0.f;
#pragma unroll
        for (int j = 0; j < 8; j++) {
#pragma unroll
            for (int kk = 0; kk < 4; kk++) {
                uint32_t bF[2];
                ldmB(bF, sBu + (uint32_t)(((kk*16 + (l & 15))*72 + j*8) << 1));
                mma16816(acc[j], aF[kk], bF);
            }
        }
        __syncthreads();
#pragma unroll
        for (int j = 0; j < 8; j++) {
            int row = r0 + (l >> 2);
            int col = j*8 + 2*(l & 3);
            *(float2*)&sO[row*68 + col]     = make_float2(acc[j][0], acc[j][1]);
            *(float2*)&sO[(row+8)*68 + col] = make_float2(acc[j][2], acc[j][3]);
        }
        __syncthreads();
        {
            int c2 = (t & 31) * 2, grp = t >> 5;
            float bb0 = sBias[c2], bb1 = sBias[c2+1];
#pragma unroll
            for (int i = 0; i < 16; i++) {
                int r = grp*16 + i;
                float2 f = *(float2*)&sO[r*68 + c2];
                __half2 o = __floats2half2_rn(fmaxf(f.x + bb0, 0.f),
                                              fmaxf(f.y + bb1, 0.f));
                *(__half2*)(g_h1 + (tile0 + r)*64 + c2) = o;
            }
        }
    } else {
        // ---------------- h2 path (gathered fp32) ----------------
        float* sIn = (float*)smem;                 // [64][68]
        float* sW  = (float*)(smem + 17408);       // [64][64]
        float* sB  = (float*)(smem + 33792);
        int*   sP  = (int*)(smem + 34048);
        int ebid = blockIdx.x - 2304;
        int np = g_npairs;
        for (int i = t; i < 4096; i += 256) sW[(i >> 6)*64 + (i & 63)] = W2[i];
        if (t < 64) {
            sB[t] = b2[t];
            int r = ebid * 64 + t;
            sP[t] = (r < np) ? g_pairs[r] : -1;
        }
        __syncthreads();
        for (int i = t; i < 1024; i += 256) {
            int r = i >> 4, j = (i & 15) << 2;
            int p = sP[r];
            float4 v = make_float4(0.f, 0.f, 0.f, 0.f);
            if (p >= 0) {
                v = *(const float4*)(Tprev + (long)p*64 + j);
                if (useNorm) {
                    int bb = p / NPAIR;
                    float4 sc = *(const float4*)(g_scale + bb*64 + j);
                    float4 sh = *(const float4*)(g_shift + bb*64 + j);
                    v.x = fmaxf(fmaf(v.x, sc.x, sh.x), 0.0f);
                    v.y = fmaxf(fmaf(v.y, sc.y, sh.y), 0.0f);
                    v.z = fmaxf(fmaf(v.z, sc.z, sh.z), 0.0f);
                    v.w = fmaxf(fmaf(v.w, sc.w, sh.w), 0.0f);
                }
            }
            sIn[r*68+j] = v.x; sIn[r*68+j+1] = v.y;
            sIn[r*68+j+2] = v.z; sIn[r*68+j+3] = v.w;
        }
        __syncthreads();

        int cg = (t & 15) * 4, rg = (t >> 4) * 4;
        float acc[4][4];
#pragma unroll
        for (int i = 0; i < 4; i++)
#pragma unroll
            for (int j = 0; j < 4; j++) acc[i][j] = 0.0f;
#pragma unroll 16
        for (int k = 0; k < 64; k++) {
            float4 wv = *(float4*)&sW[k*64 + cg];
#pragma unroll
            for (int i = 0; i < 4; i++) {
                float a = sIn[(rg + i)*68 + k];
                acc[i][0] = fmaf(a, wv.x, acc[i][0]);
                acc[i][1] = fmaf(a, wv.y, acc[i][1]);
                acc[i][2] = fmaf(a, wv.z, acc[i][2]);
                acc[i][3] = fmaf(a, wv.w, acc[i][3]);
            }
        }
        float4 bb = *(float4*)&sB[cg];
#pragma unroll
        for (int i = 0; i < 4; i++) {
            int p = sP[rg + i];
            if (p >= 0) {
                float4 o;
                o.x = fmaxf(acc[i][0] + bb.x, 0.0f);
                o.y = fmaxf(acc[i][1] + bb.y, 0.0f);
                o.z = fmaxf(acc[i][2] + bb.z, 0.0f);
                o.w = fmaxf(acc[i][3] + bb.w, 0.0f);
                *(float4*)(g_h2 + (long)p*64 + cg) = o;
            }
        }
    }
}

// ---------------------------------------------------------------------------
// k23_mma: per (b,v) block:
//   M[u,d] = sum_{w in N(v)} h1[u,w,d]*h2[w,v,d]   (fp32 regs)
//   split M -> fp16 hi/lo smem; O = M@Wm via 2x HMMA (exact M)
//   Tcur = relu_norm(Tprev) + O + bm ; per-(b,d) stats.
__global__ void __launch_bounds__(256) k23_mma(const float* __restrict__ Tprev,
                                               const float* __restrict__ Wm,
                                               const float* __restrict__ bm,
                                               int useNorm,
                                               float* __restrict__ Tcur) {
    extern __shared__ char smem[];
    __half* sWm  = (__half*)smem;                  // 64x72
    __half* sMhi = (__half*)(smem + 9216);         // 96x72
    __half* sMlo = (__half*)(smem + 23040);        // 96x72
    float*  sh2  = (float*)(smem + 36864);         // 96x64 staging
    float*  sO   = (float*)(smem + 36864);         // 96x68 (reuse)
    int*    snbr = (int*)(smem + 62976);
    float*  sSc  = (float*)(smem + 63360);
    float*  sSh  = (float*)(smem + 63616);
    float*  sSum = (float*)(smem + 63872);
    float*  sSq  = (float*)(smem + 64128);

    int t = threadIdx.x, w = t >> 5, l = t & 31;
    int b = blockIdx.x / NN, v = blockIdx.x % NN;
    int deg = g_deg[b*NN + v];

    for (int i = t; i < 4096; i += 256) {
        int k = i >> 6, n = i & 63;
        sWm[k*72 + n] = __float2half(Wm[i]);
    }
    if (t < 64) {
        sSc[t] = useNorm ? g_scale[b*64 + t] : 1.f;
        sSh[t] = useNorm ? g_shift[b*64 + t] : 0.f;
        sSum[t] = 0.f; sSq[t] = 0.f;
    }
    if (t < 96) snbr[t] = (t < deg) ? g_nbr[(b*NN + v)*NN + t] : 0;
    __syncthreads();

    for (int q = t; q < deg*16; q += 256) {
        int s = q >> 4, j = (q & 15) << 2;
        int ww = snbr[s];
        *(float4*)&sh2[s*64 + j] =
            *(const float4*)(g_h2 + ((long)(b*NPAIR + ww*NN + v) << 6) + j);
    }
    __syncthreads();

    // sparse aggregation: thread = (d0 = (t&7)*8, ug = t>>3), u = ug*3 + i
    int d0 = (t & 7) * 8, ug = t >> 3;
    float acc[3][8];
#pragma unroll
    for (int i = 0; i < 3; i++)
#pragma unroll
        for (int j = 0; j < 8; j++) acc[i][j] = 0.f;

    const __half* h1b = g_h1 + ((long)b*NPAIR)*64 + (long)(ug*3)*6144 + d0;
    for (int s = 0; s < deg; s++) {
        int ww = snbr[s];
        float4 g0 = *(float4*)&sh2[s*64 + d0];
        float4 g1 = *(float4*)&sh2[s*64 + d0 + 4];
        const __half* p0 = h1b + (long)ww*64;
#pragma unroll
        for (int i = 0; i < 3; i++) {
            uint4 au = *(const uint4*)(p0 + (long)i*6144);
            __half2* hp = (__half2*)&au;
            float2 a0 = __half22float2(hp[0]);
            float2 a1 = __half22float2(hp[1]);
            float2 a2 = __half22float2(hp[2]);
            float2 a3 = __half22float2(hp[3]);
            acc[i][0] = fmaf(a0.x, g0.x, acc[i][0]);
            acc[i][1] = fmaf(a0.y, g0.y, acc[i][1]);
            acc[i][2] = fmaf(a1.x, g0.z, acc[i][2]);
            acc[i][3] = fmaf(a1.y, g0.w, acc[i][3]);
            acc[i][4] = fmaf(a2.x, g1.x, acc[i][4]);
            acc[i][5] = fmaf(a2.y, g1.y, acc[i][5]);
            acc[i][6] = fmaf(a3.x, g1.z, acc[i][6]);
            acc[i][7] = fmaf(a3.y, g1.w, acc[i][7]);
        }
    }
    // split write M -> hi/lo fp16
#pragma unroll
    for (int i = 0; i < 3; i++) {
        int u = ug*3 + i;
        __half hh[8], hl[8];
#pragma unroll
        for (int j = 0; j < 8; j++) {
            float x = acc[i][j];
            __half h = __float2half_rn(x);
            hh[j] = h;
            hl[j] = __float2half_rn(x - __half2float(h));
        }
        *(uint4*)&sMhi[u*72 + d0] = *(uint4*)hh;
        *(uint4*)&sMlo[u*72 + d0] = *(uint4*)hl;
    }
    __syncthreads();

    // HMMA: warp w -> n-tile cols [w*8, w*8+8)
    uint32_t sMhiu = smem_u32(sMhi);
    uint32_t sMlou = smem_u32(sMlo);
    uint32_t sWmu  = smem_u32(sWm);
    uint32_t bF[4][2];
#pragma unroll
    for (int k = 0; k < 4; k++)
        ldmB(bF[k], sWmu + (uint32_t)(((k*16 + (l & 15))*72 + w*8) << 1));

#pragma unroll
    for (int m = 0; m < 6; m++) {
        float c4[4] = {0.f, 0.f, 0.f, 0.f};
        uint32_t rowoff = (uint32_t)((m*16 + (l & 15))*72 + 8*(l >> 4));
#pragma unroll
        for (int k = 0; k < 4; k++) {
            uint32_t aH[4], aL[4];
            ldmA(aH, sMhiu + ((rowoff + k*16) << 1));
            mma16816(c4, aH, bF[k]);
            ldmA(aL, sMlou + ((rowoff + k*16) << 1));
            mma16816(c4, aL, bF[k]);
        }
        int row = m*16 + (l >> 2);
        int col = w*8 + 2*(l & 3);
        *(float2*)&sO[row*68 + col]     = make_float2(c4[0], c4[1]);
        *(float2*)&sO[(row+8)*68 + col] = make_float2(c4[2], c4[3]);
    }
    __syncthreads();

    // epilogue: bias + residual(norm) + store Tcur + stats
    {
        int c2 = (t & 31) * 2, grp = t >> 5;
        float bb0 = bm[c2], bb1 = bm[c2+1];
        float sc0 = sSc[c2], sc1 = sSc[c2+1];
        float sh0 = sSh[c2], sh1 = sSh[c2+1];
        float cs0 = 0.f, cs1 = 0.f, cq0 = 0.f, cq1 = 0.f;
#pragma unroll
        for (int i = 0; i < 12; i++) {
            int u = grp*12 + i;
            long p = (long)b*NPAIR + (long)u*NN + v;
            float2 m2 = *(float2*)&sO[u*68 + c2];
            float2 tv = *(const float2*)(Tprev + p*64 + c2);
            if (useNorm) {
                tv.x = fmaxf(fmaf(tv.x, sc0, sh0), 0.f);
                tv.y = fmaxf(fmaf(tv.y, sc1, sh1), 0.f);
            }
            float o0 = m2.x + bb0 + tv.x;
            float o1 = m2.y + bb1 + tv.y;
            *(float2*)(Tcur + p*64 + c2) = make_float2(o0, o1);
            cs0 += o0; cq0 += o0*o0;
            cs1 += o1; cq1 += o1*o1;
        }
        atomicAdd(&sSum[c2],   cs0);
        atomicAdd(&sSum[c2+1], cs1);
        atomicAdd(&sSq[c2],    cq0);
        atomicAdd(&sSq[c2+1],  cq1);
    }
    __syncthreads();
    if (t < 64) {
        atomicAdd(&g_sum[b*64 + t], sSum[t]);
        atomicAdd(&g_sq [b*64 + t], sSq[t]);
    }
}

// stats + zero for next layer
__global__ void k_stats(const float* __restrict__ gamma,
                        const float* __restrict__ beta) {
    int i = blockIdx.x * 256 + threadIdx.x;
    if (i >= BB*DD) return;
    int d = i & 63;
    float mu  = g_sum[i] * (1.0f / NPAIR);
    float var = g_sq[i]  * (1.0f / NPAIR) - mu*mu;
    float s   = gamma[d] * rsqrtf(var + 1e-5f);
    g_scale[i] = s;
    g_shift[i] = beta[d] - mu * s;
    g_sum[i] = 0.f;
    g_sq[i]  = 0.f;
}

__global__ void __launch_bounds__(256) k_pool(const float* __restrict__ T) {
    __shared__ float sp[64];
    int t = threadIdx.x;
    long q = (long)blockIdx.x * 256 + t;
    long idx = q * 4;
    int d0 = (int)(idx & 63);
    int p  = (int)(idx >> 6);
    int b  = p / NPAIR;
    float4 v  = *(const float4*)(T + idx);
    float4 sc = *(const float4*)(g_scale + b*64 + d0);
    float4 sh = *(const float4*)(g_shift + b*64 + d0);
    float4 o;
    o.x = fmaxf(fmaf(v.x, sc.x, sh.x), 0.0f);
    o.y = fmaxf(fmaf(v.y, sc.y, sh.y), 0.0f);
    o.z = fmaxf(fmaf(v.z, sc.z, sh.z), 0.0f);
    o.w = fmaxf(fmaf(v.w, sc.w, sh.w), 0.0f);
    if (t < 64) sp[t] = 0.0f;
    __syncthreads();
    atomicAdd(&sp[d0+0], o.x);
    atomicAdd(&sp[d0+1], o.y);
    atomicAdd(&sp[d0+2], o.z);
    atomicAdd(&sp[d0+3], o.w);
    __syncthreads();
    if (t < 64) atomicAdd(&g_pool[b*64 + t], sp[t]);
}

__global__ void k5_out(const float* __restrict__ pw,
                       const float* __restrict__ pb,
                       float* __restrict__ out) {
    int t = threadIdx.x;
    int b = t >> 5, lane = t & 31;
    float v = g_pool[b*64 + lane]      * pw[lane]
            + g_pool[b*64 + lane + 32] * pw[lane + 32];
#pragma unroll
    for (int o = 16; o > 0; o >>= 1) v += __shfl_down_sync(0xffffffffu, v, o);
    if (lane == 0) out[b] = v + pb[0];
}

// ---------------------------------------------------------------------------
extern "C" void kernel_launch(void* const* d_in, const int* in_sizes, int n_in,
                              void* d_out, int out_size) {
    (void)in_sizes; (void)n_in; (void)out_size;
    const int*   x    = (const int*)d_in[0];
    const int*   ei   = (const int*)d_in[1];
    const int*   ea   = (const int*)d_in[2];
    const float* nemb = (const float*)d_in[3];
    const float* eemb = (const float*)d_in[4];
    const float* W1   = (const float*)d_in[5];
    const float* b1   = (const float*)d_in[6];
    const float* W2   = (const float*)d_in[7];
    const float* b2   = (const float*)d_in[8];
    const float* Wm   = (const float*)d_in[9];
    const float* bm   = (const float*)d_in[10];
    const float* gam  = (const float*)d_in[11];
    const float* bet  = (const float*)d_in[12];
    const float* pw   = (const float*)d_in[13];
    const float* pb   = (const float*)d_in[14];
    float* out = (float*)d_out;

    float* gT0; cudaGetSymbolAddress((void**)&gT0, g_T0);
    float* gT1; cudaGetSymbolAddress((void**)&gT1, g_T1);

    cudaFuncSetAttribute(k1_fused, cudaFuncAttributeMaxDynamicSharedMemorySize, SMEM_K1);
    cudaFuncSetAttribute(k23_mma,  cudaFuncAttributeMaxDynamicSharedMemorySize, SMEM_K23);

    k_init_clear<<<1152, 256>>>();
    k_scatter<<<96, 256>>>(ei, ea);
    k_decode<<<1152, 256>>>();
    k_initW<<<18432, 256>>>(x, nemb, eemb);   // -> g_T1

    for (int l = 0; l < LL; l++) {
        float* Tprev = (l % 2 == 0) ? gT1 : gT0;
        float* Tcur  = (l % 2 == 0) ? gT0 : gT1;
        int useNorm  = (l > 0) ? 1 : 0;
        k1_fused<<<3072, 256, SMEM_K1>>>(Tprev, W1 + l*4096, b1 + l*64,
                                         W2 + l*4096, b2 + l*64, useNorm);
        k23_mma<<<3072, 256, SMEM_K23>>>(Tprev, Wm + l*4096, bm + l*64,
                                         useNorm, Tcur);
        k_stats<<<8, 256>>>(gam + l*64, bet + l*64);
    }
    k_pool<<<18432, 256>>>(gT0);
    k5_out<<<1, 1024>>>(pw, pb, out);
}

// round 10
// speedup vs baseline: 1.1392x; 1.1392x over previous
#include <cuda_runtime.h>
#include <cuda_fp16.h>
#include <cstdint>
#include <stdint.h>

#define BB    32
#define NN    96
#define DD    64
#define LL    5
#define NPAIR 9216            // N*N
#define PTOT  294912          // B*N*N
#define BEP   24576           // B*EP
#define EV    5
#define MAXPAIRS 49152

// ---- scratch (device globals; no allocation allowed) ----
__device__ __align__(16) float  g_T0 [PTOT*DD];
__device__ __align__(16) float  g_T1 [PTOT*DD];
__device__ __align__(16) __half g_h1 [PTOT*DD];   // h1[b,u,w,d] fp16
__device__ __align__(16) float  g_h2 [PTOT*DD];   // h2[b,w,v,d] fp32 (edge slots)
__device__ __align__(16) __half g_M16[PTOT*DD];   // aggregation output fp16
__device__ int   g_aux[PTOT];
__device__ int   g_A  [PTOT];
__device__ int   g_deg[BB*NN];
__device__ int   g_nbr[BB*NN*NN];
__device__ int   g_pairs[MAXPAIRS];
__device__ int   g_npairs;
__device__ float g_sum[BB*DD];
__device__ float g_sq [BB*DD];
__device__ float g_scale[BB*DD];
__device__ float g_shift[BB*DD];
__device__ float g_pool[BB*DD];

// k1_fused / k3_mma dynamic smem (bytes), HMMA path:
//   [0:34816) sA(128x72 fp16) reused as sO(128x68 f32) | [34816:44032) sB(64x72 fp16)
//   [44032:44288) bias | [44288:44544) sc | [44544:44800) sh
//   [44800:45056) sSum (k3) | [45056:45312) sSq (k3)
// k1 h2 path: [0:17408) sIn 64x68 f32 | [17408:33792) sW 64x64 f32 | [33792:34048) sB | [34048:34304) sP
#define SMEM_MMA 45312

__device__ __forceinline__ uint32_t smem_u32(const void* p) {
    uint32_t a;
    asm("{ .reg .u64 t; cvta.to.shared.u64 t, %1; cvt.u32.u64 %0, t; }"
        : "=r"(a) : "l"(p));
    return a;
}
__device__ __forceinline__ void ldmA(uint32_t a[4], uint32_t addr) {
    asm volatile("ldmatrix.sync.aligned.m8n8.x4.shared.b16 {%0,%1,%2,%3}, [%4];"
        : "=r"(a[0]), "=r"(a[1]), "=r"(a[2]), "=r"(a[3]) : "r"(addr));
}
__device__ __forceinline__ void ldmB(uint32_t b[2], uint32_t addr) {
    asm volatile("ldmatrix.sync.aligned.m8n8.x2.trans.shared.b16 {%0,%1}, [%2];"
        : "=r"(b[0]), "=r"(b[1]) : "r"(addr));
}
__device__ __forceinline__ void mma16816(float c[4], const uint32_t a[4],
                                         const uint32_t b[2]) {
    asm volatile(
        "mma.sync.aligned.m16n8k16.row.col.f32.f16.f16.f32 "
        "{%0,%1,%2,%3}, {%4,%5,%6,%7}, {%8,%9}, {%0,%1,%2,%3};"
        : "+f"(c[0]), "+f"(c[1]), "+f"(c[2]), "+f"(c[3])
        : "r"(a[0]), "r"(a[1]), "r"(a[2]), "r"(a[3]), "r"(b[0]), "r"(b[1]));
}

// ---------------------------------------------------------------------------
__global__ void k_init_clear() {
    int i = blockIdx.x * 256 + threadIdx.x;
    if (i < PTOT)   g_aux[i] = -1;
    if (i < BB*DD)  { g_pool[i] = 0.0f; g_sum[i] = 0.0f; g_sq[i] = 0.0f; }
    if (i < BB*NN)  g_deg[i] = 0;
    if (i == 0)     g_npairs = 0;
}

__global__ void k_scatter(const int* __restrict__ ei, const int* __restrict__ ea) {
    int e = blockIdx.x * 256 + threadIdx.x;
    if (e >= BEP) return;
    int a = ei[e];
    int bnode = ei[BEP + e];
    int g = a / NN, u = a % NN, v = bnode % NN;
    int lab = ea[e] & 7;
    atomicMax(&g_aux[g*NPAIR + u*NN + v], (e << 3) | lab);
    atomicMax(&g_aux[g*NPAIR + v*NN + u], ((e + BEP) << 3) | lab);
}

__global__ void k_decode() {
    int i = blockIdx.x * 256 + threadIdx.x;
    if (i >= PTOT) return;
    int av = g_aux[i];
    int a  = (av < 0) ? EV : (av & 7);
    g_A[i] = a;
    if (a != EV) {
        int b = i / NPAIR, r = i % NPAIR;
        int w = r / NN, v = r % NN;
        int slot = atomicAdd(&g_deg[b*NN + v], 1);
        g_nbr[(b*NN + v)*NN + slot] = w;
        int ps = atomicAdd(&g_npairs, 1);
        g_pairs[ps] = i;
    }
}

__global__ void k_initW(const int* __restrict__ x,
                        const float* __restrict__ nemb,
                        const float* __restrict__ eemb) {
    long q = (long)blockIdx.x * 256 + threadIdx.x;
    int p  = (int)(q >> 4);
    int d0 = ((int)q & 15) << 2;
    int b = p / NPAIR, r = p % NPAIR, u = r / NN, v = r % NN;
    int xu = x[b*NN + u], xv = x[b*NN + v], a = g_A[p];
    float4 hu = *(const float4*)(nemb + xu*DD + d0);
    float4 hv = *(const float4*)(nemb + xv*DD + d0);
    float4 he = *(const float4*)(eemb + a*DD + d0);
    float4 o;
    o.x = hu.x + hv.x + he.x;
    o.y = hu.y + hv.y + he.y;
    o.z = hu.z + hv.z + he.z;
    o.w = hu.w + hv.w + he.w;
    *(float4*)(g_T1 + (long)p*DD + d0) = o;
}

// ---------------------------------------------------------------------------
// k1_fused: blocks [0,2304): h1 = relu(relu_norm(T)@W1+b1) via HMMA, fp16 out.
//           blocks [2304,3072): h2 = relu(relu_norm(T)@W2+b2), edge rows, fp32.
__global__ void __launch_bounds__(256) k1_fused(const float* __restrict__ Tprev,
                                                const float* __restrict__ W1,
                                                const float* __restrict__ b1,
                                                const float* __restrict__ W2,
                                                const float* __restrict__ b2,
                                                int useNorm) {
    extern __shared__ char smem[];
    int t = threadIdx.x;
    if (blockIdx.x < 2304) {
        // ---------------- h1 path (HMMA) ----------------
        __half* sA   = (__half*)smem;
        float*  sO   = (float*)smem;
        __half* sB   = (__half*)(smem + 34816);
        float* sBias = (float*)(smem + 44032);
        float* sSc   = (float*)(smem + 44288);
        float* sSh   = (float*)(smem + 44544);
        int w = t >> 5, l = t & 31;
        int b = blockIdx.x / 72;
        long tile0 = (long)blockIdx.x * 128;

        for (int i = t; i < 4096; i += 256) {
            int k = i >> 6, n = i & 63;
            sB[k*72 + n] = __float2half(W1[i]);
        }
        if (t < 64) {
            sBias[t] = b1[t];
            sSc[t] = useNorm ? g_scale[b*64 + t] : 1.f;
            sSh[t] = useNorm ? g_shift[b*64 + t] : 0.f;
        }
        __syncthreads();
        {
            int r = t >> 1, c0 = (t & 1) * 32;
            const float* src = Tprev + (tile0 + r) * 64 + c0;
            __half h[32];
#pragma unroll
            for (int j = 0; j < 32; j += 4) {
                float4 f = *(const float4*)(src + j);
                if (useNorm) {
                    f.x = fmaxf(fmaf(f.x, sSc[c0+j+0], sSh[c0+j+0]), 0.f);
                    f.y = fmaxf(fmaf(f.y, sSc[c0+j+1], sSh[c0+j+1]), 0.f);
                    f.z = fmaxf(fmaf(f.z, sSc[c0+j+2], sSh[c0+j+2]), 0.f);
                    f.w = fmaxf(fmaf(f.w, sSc[c0+j+3], sSh[c0+j+3]), 0.f);
                }
                h[j+0] = __float2half(f.x);
                h[j+1] = __float2half(f.y);
                h[j+2] = __float2half(f.z);
                h[j+3] = __float2half(f.w);
            }
            uint4* dst = (uint4*)(sA + r*72 + c0);
#pragma unroll
            for (int j = 0; j < 4; j++) dst[j] = ((uint4*)h)[j];
        }
        __syncthreads();

        uint32_t sAu = smem_u32(sA);
        uint32_t sBu = smem_u32(sB);
        int r0 = w * 16;
        uint32_t aF[4][4];
#pragma unroll
        for (int kk = 0; kk < 4; kk++)
            ldmA(aF[kk], sAu + (uint32_t)(((r0 + (l & 15))*72 + kk*16 + 8*(l >> 4)) << 1));

        float acc[8][4];
#pragma unroll
        for (int j = 0; j < 8; j++)
#pragma unroll
            for (int q = 0; q < 4; q++) acc[j][q] = 0.f;
#pragma unroll
        for (int j = 0; j < 8; j++) {
#pragma unroll
            for (int kk = 0; kk < 4; kk++) {
                uint32_t bF[2];
                ldmB(bF, sBu + (uint32_t)(((kk*16 + (l & 15))*72 + j*8) << 1));
                mma16816(acc[j], aF[kk], bF);
            }
        }
        __syncthreads();
#pragma unroll
        for (int j = 0; j < 8; j++) {
            int row = r0 + (l >> 2);
            int col = j*8 + 2*(l & 3);
            *(float2*)&sO[row*68 + col]     = make_float2(acc[j][0], acc[j][1]);
            *(float2*)&sO[(row+8)*68 + col] = make_float2(acc[j][2], acc[j][3]);
        }
        __syncthreads();
        {
            int c2 = (t & 31) * 2, grp = t >> 5;
            float bb0 = sBias[c2], bb1 = sBias[c2+1];
#pragma unroll
            for (int i = 0; i < 16; i++) {
                int r = grp*16 + i;
                float2 f = *(float2*)&sO[r*68 + c2];
                __half2 o = __floats2half2_rn(fmaxf(f.x + bb0, 0.f),
                                              fmaxf(f.y + bb1, 0.f));
                *(__half2*)(g_h1 + (tile0 + r)*64 + c2) = o;
            }
        }
    } else {
        // ---------------- h2 path (gathered fp32) ----------------
        float* sIn = (float*)smem;                 // [64][68]
        float* sW  = (float*)(smem + 17408);       // [64][64]
        float* sB  = (float*)(smem + 33792);
        int*   sP  = (int*)(smem + 34048);
        int ebid = blockIdx.x - 2304;
        int np = g_npairs;
        for (int i = t; i < 4096; i += 256) sW[(i >> 6)*64 + (i & 63)] = W2[i];
        if (t < 64) {
            sB[t] = b2[t];
            int r = ebid * 64 + t;
            sP[t] = (r < np) ? g_pairs[r] : -1;
        }
        __syncthreads();
        for (int i = t; i < 1024; i += 256) {
            int r = i >> 4, j = (i & 15) << 2;
            int p = sP[r];
            float4 v = make_float4(0.f, 0.f, 0.f, 0.f);
            if (p >= 0) {
                v = *(const float4*)(Tprev + (long)p*64 + j);
                if (useNorm) {
                    int bb = p / NPAIR;
                    float4 sc = *(const float4*)(g_scale + bb*64 + j);
                    float4 sh = *(const float4*)(g_shift + bb*64 + j);
                    v.x = fmaxf(fmaf(v.x, sc.x, sh.x), 0.0f);
                    v.y = fmaxf(fmaf(v.y, sc.y, sh.y), 0.0f);
                    v.z = fmaxf(fmaf(v.z, sc.z, sh.z), 0.0f);
                    v.w = fmaxf(fmaf(v.w, sc.w, sh.w), 0.0f);
                }
            }
            sIn[r*68+j] = v.x; sIn[r*68+j+1] = v.y;
            sIn[r*68+j+2] = v.z; sIn[r*68+j+3] = v.w;
        }
        __syncthreads();

        int cg = (t & 15) * 4, rg = (t >> 4) * 4;
        float acc[4][4];
#pragma unroll
        for (int i = 0; i < 4; i++)
#pragma unroll
            for (int j = 0; j < 4; j++) acc[i][j] = 0.0f;
#pragma unroll 16
        for (int k = 0; k < 64; k++) {
            float4 wv = *(float4*)&sW[k*64 + cg];
#pragma unroll
            for (int i = 0; i < 4; i++) {
                float a = sIn[(rg + i)*68 + k];
                acc[i][0] = fmaf(a, wv.x, acc[i][0]);
                acc[i][1] = fmaf(a, wv.y, acc[i][1]);
                acc[i][2] = fmaf(a, wv.z, acc[i][2]);
                acc[i][3] = fmaf(a, wv.w, acc[i][3]);
            }
        }
        float4 bb = *(float4*)&sB[cg];
#pragma unroll
        for (int i = 0; i < 4; i++) {
            int p = sP[rg + i];
            if (p >= 0) {
                float4 o;
                o.x = fmaxf(acc[i][0] + bb.x, 0.0f);
                o.y = fmaxf(acc[i][1] + bb.y, 0.0f);
                o.z = fmaxf(acc[i][2] + bb.z, 0.0f);
                o.w = fmaxf(acc[i][3] + bb.w, 0.0f);
                *(float4*)(g_h2 + (long)p*64 + cg) = o;
            }
        }
    }
}

// ---------------------------------------------------------------------------
// K2 sparse: M16[b,u,v,d] = sum_{w in N(v)} h1[b,u,w,d]*h2[b,w,v,d] (fp16 out)
// small static smem -> high occupancy; h1 loads are uint4 (8 halves).
__global__ void __launch_bounds__(256) k2_sparse() {
    __shared__ int snbr[96];
    __shared__ float sh2[96*64];
    int t = threadIdx.x;
    int b = blockIdx.x / NN, v = blockIdx.x % NN;
    int deg = g_deg[b*NN + v];
    if (t < 96) snbr[t] = (t < deg) ? g_nbr[(b*NN + v)*NN + t] : 0;
    __syncthreads();
    for (int q = t; q < deg*16; q += 256) {
        int s = q >> 4, j = (q & 15) << 2;
        int w = snbr[s];
        *(float4*)&sh2[s*64 + j] =
            *(const float4*)(g_h2 + ((long)(b*NPAIR + w*NN + v) << 6) + j);
    }
    __syncthreads();

    // thread = (d0 = (t&7)*8, ug = t>>3); each ug owns 3 u's
    int d0 = (t & 7) * 8, ug = t >> 3;
    float acc[3][8];
#pragma unroll
    for (int i = 0; i < 3; i++)
#pragma unroll
        for (int j = 0; j < 8; j++) acc[i][j] = 0.f;

    const __half* h1b = g_h1 + ((long)b*NPAIR)*64 + (long)(ug*3)*6144 + d0;
    for (int s = 0; s < deg; s++) {
        int w = snbr[s];
        float4 g0 = *(float4*)&sh2[s*64 + d0];
        float4 g1 = *(float4*)&sh2[s*64 + d0 + 4];
        const __half* p0 = h1b + (long)w*64;
#pragma unroll
        for (int i = 0; i < 3; i++) {
            uint4 au = *(const uint4*)(p0 + (long)i*6144);
            __half2* hp = (__half2*)&au;
            float2 a0 = __half22float2(hp[0]);
            float2 a1 = __half22float2(hp[1]);
            float2 a2 = __half22float2(hp[2]);
            float2 a3 = __half22float2(hp[3]);
            acc[i][0] = fmaf(a0.x, g0.x, acc[i][0]);
            acc[i][1] = fmaf(a0.y, g0.y, acc[i][1]);
            acc[i][2] = fmaf(a1.x, g0.z, acc[i][2]);
            acc[i][3] = fmaf(a1.y, g0.w, acc[i][3]);
            acc[i][4] = fmaf(a2.x, g1.x, acc[i][4]);
            acc[i][5] = fmaf(a2.y, g1.y, acc[i][5]);
            acc[i][6] = fmaf(a3.x, g1.z, acc[i][6]);
            acc[i][7] = fmaf(a3.y, g1.w, acc[i][7]);
        }
    }
    __half* Mb = g_M16 + ((long)(b*NPAIR + v))*64 + (long)(ug*3)*6144 + d0;
#pragma unroll
    for (int i = 0; i < 3; i++) {
        __half hh[8];
#pragma unroll
        for (int j = 0; j < 8; j++) hh[j] = __float2half_rn(acc[i][j]);
        *(uint4*)(Mb + (long)i*6144) = *(uint4*)hh;
    }
}

// ---------------------------------------------------------------------------
// k3_mma: Tcur = relu_norm(Tprev) + M16@Wm + bm, HMMA; per-(b,d) stats.
__global__ void __launch_bounds__(256) k3_mma(const float* __restrict__ Tprev,
                                              const float* __restrict__ Wm,
                                              const float* __restrict__ bm,
                                              int useNorm,
                                              float* __restrict__ Tcur) {
    extern __shared__ char smem[];
    __half* sA   = (__half*)smem;
    float*  sO   = (float*)smem;
    __half* sB   = (__half*)(smem + 34816);
    float* sBm   = (float*)(smem + 44032);
    float* sSc   = (float*)(smem + 44288);
    float* sSh   = (float*)(smem + 44544);
    float* sSum  = (float*)(smem + 44800);
    float* sSq   = (float*)(smem + 45056);
    int t = threadIdx.x, w = t >> 5, l = t & 31;
    int b = blockIdx.x / 72;
    long tile0 = (long)blockIdx.x * 128;

    for (int i = t; i < 4096; i += 256) {
        int k = i >> 6, n = i & 63;
        sB[k*72 + n] = __float2half(Wm[i]);
    }
    if (t < 64) {
        sBm[t] = bm[t];
        sSc[t] = useNorm ? g_scale[b*64 + t] : 1.f;
        sSh[t] = useNorm ? g_shift[b*64 + t] : 0.f;
        sSum[t] = 0.f;
        sSq[t] = 0.f;
    }
    {
        int r = t >> 1, c0 = (t & 1) * 32;
        const uint4* src = (const uint4*)(g_M16 + (tile0 + r)*64 + c0);
        uint4* dst = (uint4*)(sA + r*72 + c0);
#pragma unroll
        for (int j = 0; j < 4; j++) dst[j] = src[j];
    }
    __syncthreads();

    uint32_t sAu = smem_u32(sA);
    uint32_t sBu = smem_u32(sB);
    int r0 = w * 16;
    uint32_t aF[4][4];
#pragma unroll
    for (int kk = 0; kk < 4; kk++)
        ldmA(aF[kk], sAu + (uint32_t)(((r0 + (l & 15))*72 + kk*16 + 8*(l >> 4)) << 1));

    float acc[8][4];
#pragma unroll
    for (int j = 0; j < 8; j++)
#pragma unroll
        for (int q = 0; q < 4; q++) acc[j][q] = 0.f;

#pragma unroll
    for (int j = 0; j < 8; j++) {
#pragma unroll
        for (int kk = 0; kk < 4; kk++) {
            uint32_t bF[2];
            ldmB(bF, sBu + (uint32_t)(((kk*16 + (l & 15))*72 + j*8) << 1));
            mma16816(acc[j], aF[kk], bF);
        }
    }
    __syncthreads();
#pragma unroll
    for (int j = 0; j < 8; j++) {
        int row = r0 + (l >> 2);
        int col = j*8 + 2*(l & 3);
        *(float2*)&sO[row*68 + col]     = make_float2(acc[j][0], acc[j][1]);
        *(float2*)&sO[(row+8)*68 + col] = make_float2(acc[j][2], acc[j][3]);
    }
    __syncthreads();
    {
        int c2 = (t & 31) * 2, grp = t >> 5;
        float b0 = sBm[c2], b1 = sBm[c2+1];
        float sc0 = sSc[c2], sc1 = sSc[c2+1];
        float sh0 = sSh[c2], sh1 = sSh[c2+1];
        float cs0 = 0.f, cs1 = 0.f, cq0 = 0.f, cq1 = 0.f;
#pragma unroll
        for (int i = 0; i < 16; i++) {
            int r = grp*16 + i;
            long p = tile0 + r;
            float2 m = *(float2*)&sO[r*68 + c2];
            float2 tv = *(const float2*)(Tprev + p*64 + c2);
            if (useNorm) {
                tv.x = fmaxf(fmaf(tv.x, sc0, sh0), 0.f);
                tv.y = fmaxf(fmaf(tv.y, sc1, sh1), 0.f);
            }
            float o0 = m.x + b0 + tv.x;
            float o1 = m.y + b1 + tv.y;
            *(float2*)(Tcur + p*64 + c2) = make_float2(o0, o1);
            cs0 += o0; cq0 += o0*o0;
            cs1 += o1; cq1 += o1*o1;
        }
        atomicAdd(&sSum[c2],   cs0);
        atomicAdd(&sSum[c2+1], cs1);
        atomicAdd(&sSq[c2],    cq0);
        atomicAdd(&sSq[c2+1],  cq1);
    }
    __syncthreads();
    if (t < 64) {
        atomicAdd(&g_sum[b*64 + t], sSum[t]);
        atomicAdd(&g_sq [b*64 + t], sSq[t]);
    }
}

// stats + zero for next layer
__global__ void k_stats(const float* __restrict__ gamma,
                        const float* __restrict__ beta) {
    int i = blockIdx.x * 256 + threadIdx.x;
    if (i >= BB*DD) return;
    int d = i & 63;
    float mu  = g_sum[i] * (1.0f / NPAIR);
    float var = g_sq[i]  * (1.0f / NPAIR) - mu*mu;
    float s   = gamma[d] * rsqrtf(var + 1e-5f);
    g_scale[i] = s;
    g_shift[i] = beta[d] - mu * s;
    g_sum[i] = 0.f;
    g_sq[i]  = 0.f;
}

__global__ void __launch_bounds__(256) k_pool(const float* __restrict__ T) {
    __shared__ float sp[64];
    int t = threadIdx.x;
    long q = (long)blockIdx.x * 256 + t;
    long idx = q * 4;
    int d0 = (int)(idx & 63);
    int p  = (int)(idx >> 6);
    int b  = p / NPAIR;
    float4 v  = *(const float4*)(T + idx);
    float4 sc = *(const float4*)(g_scale + b*64 + d0);
    float4 sh = *(const float4*)(g_shift + b*64 + d0);
    float4 o;
    o.x = fmaxf(fmaf(v.x, sc.x, sh.x), 0.0f);
    o.y = fmaxf(fmaf(v.y, sc.y, sh.y), 0.0f);
    o.z = fmaxf(fmaf(v.z, sc.z, sh.z), 0.0f);
    o.w = fmaxf(fmaf(v.w, sc.w, sh.w), 0.0f);
    if (t < 64) sp[t] = 0.0f;
    __syncthreads();
    atomicAdd(&sp[d0+0], o.x);
    atomicAdd(&sp[d0+1], o.y);
    atomicAdd(&sp[d0+2], o.z);
    atomicAdd(&sp[d0+3], o.w);
    __syncthreads();
    if (t < 64) atomicAdd(&g_pool[b*64 + t], sp[t]);
}

__global__ void k5_out(const float* __restrict__ pw,
                       const float* __restrict__ pb,
                       float* __restrict__ out) {
    int t = threadIdx.x;
    int b = t >> 5, lane = t & 31;
    float v = g_pool[b*64 + lane]      * pw[lane]
            + g_pool[b*64 + lane + 32] * pw[lane + 32];
#pragma unroll
    for (int o = 16; o > 0; o >>= 1) v += __shfl_down_sync(0xffffffffu, v, o);
    if (lane == 0) out[b] = v + pb[0];
}

// ---------------------------------------------------------------------------
extern "C" void kernel_launch(void* const* d_in, const int* in_sizes, int n_in,
                              void* d_out, int out_size) {
    (void)in_sizes; (void)n_in; (void)out_size;
    const int*   x    = (const int*)d_in[0];
    const int*   ei   = (const int*)d_in[1];
    const int*   ea   = (const int*)d_in[2];
    const float* nemb = (const float*)d_in[3];
    const float* eemb = (const float*)d_in[4];
    const float* W1   = (const float*)d_in[5];
    const float* b1   = (const float*)d_in[6];
    const float* W2   = (const float*)d_in[7];
    const float* b2   = (const float*)d_in[8];
    const float* Wm   = (const float*)d_in[9];
    const float* bm   = (const float*)d_in[10];
    const float* gam  = (const float*)d_in[11];
    const float* bet  = (const float*)d_in[12];
    const float* pw   = (const float*)d_in[13];
    const float* pb   = (const float*)d_in[14];
    float* out = (float*)d_out;

    float* gT0; cudaGetSymbolAddress((void**)&gT0, g_T0);
    float* gT1; cudaGetSymbolAddress((void**)&gT1, g_T1);

    cudaFuncSetAttribute(k1_fused, cudaFuncAttributeMaxDynamicSharedMemorySize, SMEM_MMA);
    cudaFuncSetAttribute(k3_mma,   cudaFuncAttributeMaxDynamicSharedMemorySize, SMEM_MMA);

    k_init_clear<<<1152, 256>>>();
    k_scatter<<<96, 256>>>(ei, ea);
    k_decode<<<1152, 256>>>();
    k_initW<<<18432, 256>>>(x, nemb, eemb);   // -> g_T1

    for (int l = 0; l < LL; l++) {
        float* Tprev = (l % 2 == 0) ? gT1 : gT0;
        float* Tcur  = (l % 2 == 0) ? gT0 : gT1;
        int useNorm  = (l > 0) ? 1 : 0;
        k1_fused<<<3072, 256, SMEM_MMA>>>(Tprev, W1 + l*4096, b1 + l*64,
                                          W2 + l*4096, b2 + l*64, useNorm);
        k2_sparse<<<3072, 256>>>();
        k3_mma<<<2304, 256, SMEM_MMA>>>(Tprev, Wm + l*4096, bm + l*64,
                                        useNorm, Tcur);
        k_stats<<<8, 256>>>(gam + l*64, bet + l*64);
    }
    k_pool<<<18432, 256>>>(gT0);
    k5_out<<<1, 1024>>>(pw, pb, out);
}